// round 1
// baseline (speedup 1.0000x reference)
#include <cuda_runtime.h>
#include <cuda_bf16.h>
#include <math.h>

#define D_MODEL 1024
#define NHEAD 16
#define HEAD_DIM 64
#define MLP_DIM 4096
#define BATCH 2
#define SEQ 2048
#define ROWS (BATCH * SEQ)   // 4096

// ---------------- scratch buffers (device globals; no allocation) -------------
__device__ float g_x[ROWS * D_MODEL];      // ln1 output
__device__ float g_q[ROWS * D_MODEL];
__device__ float g_k[ROWS * D_MODEL];
__device__ float g_v[ROWS * D_MODEL];
__device__ float g_att[ROWS * D_MODEL];
__device__ float g_mlpin[ROWS * D_MODEL];  // attn@Wo + inputs (residual 1)
__device__ float g_ln2[ROWS * D_MODEL];
__device__ float g_h[ROWS * MLP_DIM];      // gelu(fc2)

// ---------------- LayerNorm ----------------
__global__ __launch_bounds__(256) void ln_kernel(const float* __restrict__ x,
                                                 const float* __restrict__ g,
                                                 const float* __restrict__ b,
                                                 float* __restrict__ out) {
    __shared__ float red[16];
    __shared__ float stats[2];
    int row = blockIdx.x;
    int tid = threadIdx.x;
    const float4* xr = (const float4*)(x + (size_t)row * D_MODEL);
    float4 v = xr[tid];
    float s  = v.x + v.y + v.z + v.w;
    float sq = v.x * v.x + v.y * v.y + v.z * v.z + v.w * v.w;
    // warp reduce
    #pragma unroll
    for (int o = 16; o > 0; o >>= 1) {
        s  += __shfl_xor_sync(0xffffffffu, s, o);
        sq += __shfl_xor_sync(0xffffffffu, sq, o);
    }
    int warp = tid >> 5, lane = tid & 31;
    if (lane == 0) { red[warp] = s; red[warp + 8] = sq; }
    __syncthreads();
    if (tid == 0) {
        float ts = 0.f, tq = 0.f;
        #pragma unroll
        for (int i = 0; i < 8; i++) { ts += red[i]; tq += red[i + 8]; }
        float mean = ts * (1.0f / D_MODEL);
        float var  = tq * (1.0f / D_MODEL) - mean * mean;
        stats[0] = mean;
        stats[1] = rsqrtf(var + 1e-5f);
    }
    __syncthreads();
    float mean = stats[0], inv = stats[1];
    const float4* gr = (const float4*)g;
    const float4* br = (const float4*)b;
    float4 gv = gr[tid], bv = br[tid];
    float4 ov;
    ov.x = (v.x - mean) * inv * gv.x + bv.x;
    ov.y = (v.y - mean) * inv * gv.y + bv.y;
    ov.z = (v.z - mean) * inv * gv.z + bv.z;
    ov.w = (v.w - mean) * inv * gv.w + bv.w;
    ((float4*)(out + (size_t)row * D_MODEL))[tid] = ov;
}

// ---------------- GEMM: C[M,N] = A[M,K] @ B[K,N] (+epilogue) ----------------
// EPI: 0 = none, 1 = +res, 2 = +bias then gelu, 3 = +bias +res
__device__ __forceinline__ float gelu_exact(float x) {
    return 0.5f * x * (1.0f + erff(x * 0.70710678118654752f));
}

template <int EPI>
__global__ __launch_bounds__(256) void gemm_kernel(
    const float* __restrict__ A, const float* __restrict__ B,
    const float* __restrict__ bias, const float* __restrict__ res,
    float* __restrict__ C, int M, int N, int K)
{
    __shared__ float As[8][128];
    __shared__ float Bs[8][128];
    int tid = threadIdx.x;
    int bx = blockIdx.x, by = blockIdx.y;

    int arow = tid >> 1;              // 0..127
    int acol = (tid & 1) * 4;         // 0 or 4
    int brow = tid >> 5;              // 0..7
    int bcol = (tid & 31) * 4;        // 0..124

    const float* Ag = A + (size_t)(by * 128 + arow) * K + acol;
    const float* Bg = B + (size_t)brow * N + bx * 128 + bcol;

    int ry = (tid >> 4) * 4;          // 0..60
    int cx = (tid & 15) * 4;          // 0..60

    float c[8][8];
    #pragma unroll
    for (int i = 0; i < 8; i++)
        #pragma unroll
        for (int j = 0; j < 8; j++) c[i][j] = 0.f;

    for (int k0 = 0; k0 < K; k0 += 8) {
        float4 av = *(const float4*)(Ag + k0);
        float4 bv = *(const float4*)(Bg + (size_t)k0 * N);
        As[acol + 0][arow] = av.x;
        As[acol + 1][arow] = av.y;
        As[acol + 2][arow] = av.z;
        As[acol + 3][arow] = av.w;
        *(float4*)&Bs[brow][bcol] = bv;
        __syncthreads();
        #pragma unroll
        for (int kk = 0; kk < 8; kk++) {
            float a[8], b[8];
            *(float4*)&a[0] = *(float4*)&As[kk][ry];
            *(float4*)&a[4] = *(float4*)&As[kk][ry + 64];
            *(float4*)&b[0] = *(float4*)&Bs[kk][cx];
            *(float4*)&b[4] = *(float4*)&Bs[kk][cx + 64];
            #pragma unroll
            for (int i = 0; i < 8; i++)
                #pragma unroll
                for (int j = 0; j < 8; j++)
                    c[i][j] += a[i] * b[j];
        }
        __syncthreads();
    }

    int row0 = by * 128, col0 = bx * 128;
    #pragma unroll
    for (int ii = 0; ii < 2; ii++) {
        #pragma unroll
        for (int i = 0; i < 4; i++) {
            int r = row0 + ii * 64 + ry + i;
            #pragma unroll
            for (int jj = 0; jj < 2; jj++) {
                int cb = col0 + jj * 64 + cx;
                float vals[4];
                #pragma unroll
                for (int j = 0; j < 4; j++) {
                    float v = c[ii * 4 + i][jj * 4 + j];
                    if (EPI == 2 || EPI == 3) v += bias[cb + j];
                    if (EPI == 2) v = gelu_exact(v);
                    if (EPI == 1 || EPI == 3) v += res[(size_t)r * N + cb + j];
                    vals[j] = v;
                }
                *(float4*)&C[(size_t)r * N + cb] = *(float4*)vals;
            }
        }
    }
}

// ---------------- RoPE (in-place on q and k) ----------------
__global__ __launch_bounds__(256) void rope_kernel(float* __restrict__ q,
                                                   float* __restrict__ k) {
    int idx = blockIdx.x * blockDim.x + threadIdx.x;    // ROWS*NHEAD*32
    if (idx >= ROWS * NHEAD * 32) return;
    int pair = idx & 31;
    int h = (idx >> 5) & 15;
    int row = idx >> 9;
    int s = row & (SEQ - 1);
    float inv_freq = 1.0f / powf(10000.0f, (float)(2 * pair) * (1.0f / 64.0f));
    float f = (float)s * inv_freq;
    float cs = cosf(f), sn = sinf(f);
    size_t base = (size_t)row * D_MODEL + h * HEAD_DIM + 2 * pair;
    float q0 = q[base], q1 = q[base + 1];
    q[base]     = q0 * cs - q1 * sn;
    q[base + 1] = q1 * cs + q0 * sn;
    float k0 = k[base], k1 = k[base + 1];
    k[base]     = k0 * cs - k1 * sn;
    k[base + 1] = k1 * cs + k0 * sn;
}

// ---------------- Flash attention (fp32, non-causal) ----------------
// grid: (SEQ/128, BATCH*NHEAD); block: 128 threads; one q row per thread.
__global__ __launch_bounds__(128, 1) void attn_kernel(const float* __restrict__ q,
                                                      const float* __restrict__ k,
                                                      const float* __restrict__ v,
                                                      float* __restrict__ out) {
    __shared__ float smem[8192];   // 32 KB: Qt staging, then K(16K)+V(16K), then Ot
    float* Ks = smem;              // [64][64]
    float* Vs = smem + 4096;       // [64][64]
    int t = threadIdx.x;
    int qtile = blockIdx.x;
    int bh = blockIdx.y;
    int b = bh >> 4, h = bh & 15;
    int hoff = h * HEAD_DIM;
    int qrow0 = b * SEQ + qtile * 128;

    float qreg[HEAD_DIM];
    {   // coalesced load into transposed smem, then conflict-free reg copy
        float* Qt = smem;          // [64][128]
        for (int i = t; i < 128 * 64; i += 128) {
            int r = i >> 6, d = i & 63;
            Qt[d * 128 + r] = q[(size_t)(qrow0 + r) * D_MODEL + hoff + d];
        }
        __syncthreads();
        #pragma unroll
        for (int d = 0; d < HEAD_DIM; d++) qreg[d] = Qt[d * 128 + t];
        __syncthreads();
    }

    float o[HEAD_DIM];
    #pragma unroll
    for (int d = 0; d < HEAD_DIM; d++) o[d] = 0.f;
    float m = -1e30f, l = 0.f;

    for (int kt = 0; kt < SEQ / 64; kt++) {
        for (int i = t; i < 64 * 64; i += 128) {
            int r = i >> 6, d = i & 63;
            size_t g = (size_t)(b * SEQ + kt * 64 + r) * D_MODEL + hoff + d;
            Ks[i] = k[g];
            Vs[i] = v[g];
        }
        __syncthreads();
        #pragma unroll 4
        for (int j = 0; j < 64; j += 4) {
            const float* k0 = Ks + j * 64;
            const float* k1 = k0 + 64;
            const float* k2 = k0 + 128;
            const float* k3 = k0 + 192;
            float s0 = 0.f, s1 = 0.f, s2 = 0.f, s3 = 0.f;
            #pragma unroll
            for (int d = 0; d < HEAD_DIM; d++) {
                float qd = qreg[d];
                s0 += qd * k0[d];
                s1 += qd * k1[d];
                s2 += qd * k2[d];
                s3 += qd * k3[d];
            }
            s0 *= 0.125f; s1 *= 0.125f; s2 *= 0.125f; s3 *= 0.125f;
            float mn = fmaxf(fmaxf(s0, s1), fmaxf(s2, s3));
            if (mn > m) {
                float corr = expf(m - mn);
                l *= corr;
                #pragma unroll
                for (int d = 0; d < HEAD_DIM; d++) o[d] *= corr;
                m = mn;
            }
            float p0 = expf(s0 - m), p1 = expf(s1 - m);
            float p2 = expf(s2 - m), p3 = expf(s3 - m);
            l += p0 + p1 + p2 + p3;
            const float* v0 = Vs + j * 64;
            const float* v1 = v0 + 64;
            const float* v2 = v0 + 128;
            const float* v3 = v0 + 192;
            #pragma unroll
            for (int d = 0; d < HEAD_DIM; d++)
                o[d] += p0 * v0[d] + p1 * v1[d] + p2 * v2[d] + p3 * v3[d];
        }
        __syncthreads();
    }

    float inv_l = 1.0f / l;
    float* Ot = smem;              // [64][128]
    #pragma unroll
    for (int d = 0; d < HEAD_DIM; d++) Ot[d * 128 + t] = o[d] * inv_l;
    __syncthreads();
    for (int i = t; i < 128 * 64; i += 128) {
        int r = i >> 6, d = i & 63;
        out[(size_t)(qrow0 + r) * D_MODEL + hoff + d] = Ot[d * 128 + r];
    }
}

// ---------------- launch ----------------
extern "C" void kernel_launch(void* const* d_in, const int* in_sizes, int n_in,
                              void* d_out, int out_size) {
    const float* inputs = (const float*)d_in[0];
    const float* ln1_g  = (const float*)d_in[1];
    const float* ln1_b  = (const float*)d_in[2];
    const float* Wq     = (const float*)d_in[3];
    const float* Wk     = (const float*)d_in[4];
    const float* Wv     = (const float*)d_in[5];
    const float* Wo     = (const float*)d_in[6];
    const float* ln2_g  = (const float*)d_in[7];
    const float* ln2_b  = (const float*)d_in[8];
    const float* Wfc2   = (const float*)d_in[9];
    const float* bfc2   = (const float*)d_in[10];
    const float* Wfc3   = (const float*)d_in[11];
    const float* bfc3   = (const float*)d_in[12];
    float* out = (float*)d_out;

    float *px, *pq, *pk, *pv, *patt, *pmlp, *pln2, *ph;
    cudaGetSymbolAddress((void**)&px,   g_x);
    cudaGetSymbolAddress((void**)&pq,   g_q);
    cudaGetSymbolAddress((void**)&pk,   g_k);
    cudaGetSymbolAddress((void**)&pv,   g_v);
    cudaGetSymbolAddress((void**)&patt, g_att);
    cudaGetSymbolAddress((void**)&pmlp, g_mlpin);
    cudaGetSymbolAddress((void**)&pln2, g_ln2);
    cudaGetSymbolAddress((void**)&ph,   g_h);

    // 1. x = LN1(inputs)
    ln_kernel<<<ROWS, 256>>>(inputs, ln1_g, ln1_b, px);

    // 2. q/k/v = x @ W{q,k,v}
    dim3 gqkv(D_MODEL / 128, ROWS / 128);
    gemm_kernel<0><<<gqkv, 256>>>(px, Wq, nullptr, nullptr, pq, ROWS, D_MODEL, D_MODEL);
    gemm_kernel<0><<<gqkv, 256>>>(px, Wk, nullptr, nullptr, pk, ROWS, D_MODEL, D_MODEL);
    gemm_kernel<0><<<gqkv, 256>>>(px, Wv, nullptr, nullptr, pv, ROWS, D_MODEL, D_MODEL);

    // 3. RoPE in-place on q,k
    int nrope = ROWS * NHEAD * 32;
    rope_kernel<<<(nrope + 255) / 256, 256>>>(pq, pk);

    // 4. attention
    attn_kernel<<<dim3(SEQ / 128, BATCH * NHEAD), 128>>>(pq, pk, pv, patt);

    // 5. mlp_in = attn @ Wo + inputs
    gemm_kernel<1><<<gqkv, 256>>>(patt, Wo, nullptr, inputs, pmlp, ROWS, D_MODEL, D_MODEL);

    // 6. ln2
    ln_kernel<<<ROWS, 256>>>(pmlp, ln2_g, ln2_b, pln2);

    // 7. h = gelu(ln2 @ Wfc2 + bfc2)
    gemm_kernel<2><<<dim3(MLP_DIM / 128, ROWS / 128), 256>>>(
        pln2, Wfc2, bfc2, nullptr, ph, ROWS, MLP_DIM, D_MODEL);

    // 8. out = h @ Wfc3 + bfc3 + mlp_in
    gemm_kernel<3><<<dim3(D_MODEL / 128, ROWS / 128), 256>>>(
        ph, Wfc3, bfc3, pmlp, out, ROWS, D_MODEL, MLP_DIM);
}

// round 5
// speedup vs baseline: 1.1022x; 1.1022x over previous
#include <cuda_runtime.h>
#include <cuda_bf16.h>
#include <math.h>
#include <stdint.h>

#define D_MODEL 1024
#define NHEAD 16
#define HEAD_DIM 64
#define MLP_DIM 4096
#define BATCH 2
#define SEQ 2048
#define ROWS (BATCH * SEQ)   // 4096

// ---------------- scratch buffers (device globals; no allocation) -------------
__device__ float g_x[ROWS * D_MODEL];      // ln1 output
__device__ float g_q[ROWS * D_MODEL];
__device__ float g_k[ROWS * D_MODEL];
__device__ float g_v[ROWS * D_MODEL];
__device__ float g_att[ROWS * D_MODEL];
__device__ float g_mlpin[ROWS * D_MODEL];  // attn@Wo + inputs (residual 1)
__device__ float g_ln2[ROWS * D_MODEL];
__device__ float g_h[ROWS * MLP_DIM];      // gelu(fc2)

// ---------------- LayerNorm ----------------
__global__ __launch_bounds__(256) void ln_kernel(const float* __restrict__ x,
                                                 const float* __restrict__ g,
                                                 const float* __restrict__ b,
                                                 float* __restrict__ out) {
    __shared__ float red[16];
    __shared__ float stats[2];
    int row = blockIdx.x;
    int tid = threadIdx.x;
    const float4* xr = (const float4*)(x + (size_t)row * D_MODEL);
    float4 v = xr[tid];
    float s  = v.x + v.y + v.z + v.w;
    float sq = v.x * v.x + v.y * v.y + v.z * v.z + v.w * v.w;
    #pragma unroll
    for (int o = 16; o > 0; o >>= 1) {
        s  += __shfl_xor_sync(0xffffffffu, s, o);
        sq += __shfl_xor_sync(0xffffffffu, sq, o);
    }
    int warp = tid >> 5, lane = tid & 31;
    if (lane == 0) { red[warp] = s; red[warp + 8] = sq; }
    __syncthreads();
    if (tid == 0) {
        float ts = 0.f, tq = 0.f;
        #pragma unroll
        for (int i = 0; i < 8; i++) { ts += red[i]; tq += red[i + 8]; }
        float mean = ts * (1.0f / D_MODEL);
        float var  = tq * (1.0f / D_MODEL) - mean * mean;
        stats[0] = mean;
        stats[1] = rsqrtf(var + 1e-5f);
    }
    __syncthreads();
    float mean = stats[0], inv = stats[1];
    const float4* gr = (const float4*)g;
    const float4* br = (const float4*)b;
    float4 gv = gr[tid], bv = br[tid];
    float4 ov;
    ov.x = (v.x - mean) * inv * gv.x + bv.x;
    ov.y = (v.y - mean) * inv * gv.y + bv.y;
    ov.z = (v.z - mean) * inv * gv.z + bv.z;
    ov.w = (v.w - mean) * inv * gv.w + bv.w;
    ((float4*)(out + (size_t)row * D_MODEL))[tid] = ov;
}

// ---------------- tf32 tensor-core GEMM ----------------
// C[M,N] = A[M,K] @ B[K,N] (+epilogue)
// EPI: 0 = none, 1 = +res, 2 = +bias then gelu, 3 = +bias +res
__device__ __forceinline__ float gelu_exact(float x) {
    return 0.5f * x * (1.0f + erff(x * 0.70710678118654752f));
}

__device__ __forceinline__ float to_tf32(float x) {
    uint32_t r;
    asm("cvt.rna.tf32.f32 %0, %1;" : "=r"(r) : "f"(x));
    return __uint_as_float(r);
}

#define ASTRIDE 36
#define BSTRIDE 136
#define ABUF (128 * ASTRIDE)
#define BBUF (32 * BSTRIDE)
#define GEMM_SMEM ((2 * ABUF + 2 * BBUF) * 4)

template <int EPI>
__global__ __launch_bounds__(256) void gemm_tf32(
    const float* __restrict__ A, const float* __restrict__ B,
    const float* __restrict__ bias, const float* __restrict__ res,
    float* __restrict__ C, int M, int N, int K)
{
    extern __shared__ float smem[];
    float* As = smem;                  // [2][128][36]
    float* Bs = smem + 2 * ABUF;       // [2][32][136]

    int tid = threadIdx.x;
    int lane = tid & 31, wid = tid >> 5;
    int g = lane >> 2, l = lane & 3;
    int wm = (wid & 1) * 64;           // warp row offset within block
    int wn = (wid >> 1) * 32;          // warp col offset within block

    int bx = blockIdx.x, by = blockIdx.y;

    // gmem staging indices
    int ar = tid >> 1;                 // 0..127
    int ac = (tid & 1) * 16;           // 0 / 16
    int br = tid >> 3;                 // 0..31
    int bc = (tid & 7) * 16;           // 0..112

    const float* Ag = A + (size_t)(by * 128 + ar) * K + ac;
    const float* Bg = B + (size_t)br * N + bx * 128 + bc;

    float4 pa[4], pb[4];
    #pragma unroll
    for (int i = 0; i < 4; i++) {
        pa[i] = *(const float4*)(Ag + i * 4);
        pb[i] = *(const float4*)(Bg + i * 4);
    }

    float acc[4][4][4];
    #pragma unroll
    for (int mi = 0; mi < 4; mi++)
        #pragma unroll
        for (int nj = 0; nj < 4; nj++)
            #pragma unroll
            for (int r = 0; r < 4; r++) acc[mi][nj][r] = 0.f;

    int nIter = K / 32;
    int buf = 0;

    // store tile 0 (convert to tf32 on the way in)
    {
        float* as = As + ar * ASTRIDE + ac;
        float* bs = Bs + br * BSTRIDE + bc;
        #pragma unroll
        for (int i = 0; i < 4; i++) {
            float4 t;
            t.x = to_tf32(pa[i].x); t.y = to_tf32(pa[i].y);
            t.z = to_tf32(pa[i].z); t.w = to_tf32(pa[i].w);
            *(float4*)(as + i * 4) = t;
            float4 u;
            u.x = to_tf32(pb[i].x); u.y = to_tf32(pb[i].y);
            u.z = to_tf32(pb[i].z); u.w = to_tf32(pb[i].w);
            *(float4*)(bs + i * 4) = u;
        }
    }
    __syncthreads();

    for (int it = 0; it < nIter; it++) {
        if (it + 1 < nIter) {
            int k0 = (it + 1) * 32;
            #pragma unroll
            for (int i = 0; i < 4; i++) {
                pa[i] = *(const float4*)(Ag + k0 + i * 4);
                pb[i] = *(const float4*)(Bg + (size_t)k0 * N + i * 4);
            }
        }

        const float* ab = As + buf * ABUF;
        const float* bb = Bs + buf * BBUF;
        #pragma unroll
        for (int ks = 0; ks < 4; ks++) {
            int k8 = ks * 8;
            uint32_t af[4][4], bf[4][2];
            #pragma unroll
            for (int mi = 0; mi < 4; mi++) {
                const float* p = ab + (wm + mi * 16 + g) * ASTRIDE + k8 + l;
                af[mi][0] = __float_as_uint(p[0]);
                af[mi][1] = __float_as_uint(p[8 * ASTRIDE]);
                af[mi][2] = __float_as_uint(p[4]);
                af[mi][3] = __float_as_uint(p[8 * ASTRIDE + 4]);
            }
            #pragma unroll
            for (int nj = 0; nj < 4; nj++) {
                const float* p = bb + (k8 + l) * BSTRIDE + wn + nj * 8 + g;
                bf[nj][0] = __float_as_uint(p[0]);
                bf[nj][1] = __float_as_uint(p[4 * BSTRIDE]);
            }
            #pragma unroll
            for (int mi = 0; mi < 4; mi++)
                #pragma unroll
                for (int nj = 0; nj < 4; nj++) {
                    asm volatile(
                        "mma.sync.aligned.m16n8k8.row.col.f32.tf32.tf32.f32 "
                        "{%0,%1,%2,%3}, {%4,%5,%6,%7}, {%8,%9}, {%0,%1,%2,%3};"
                        : "+f"(acc[mi][nj][0]), "+f"(acc[mi][nj][1]),
                          "+f"(acc[mi][nj][2]), "+f"(acc[mi][nj][3])
                        : "r"(af[mi][0]), "r"(af[mi][1]),
                          "r"(af[mi][2]), "r"(af[mi][3]),
                          "r"(bf[nj][0]), "r"(bf[nj][1]));
                }
        }

        if (it + 1 < nIter) {
            float* as = As + (buf ^ 1) * ABUF + ar * ASTRIDE + ac;
            float* bs = Bs + (buf ^ 1) * BBUF + br * BSTRIDE + bc;
            #pragma unroll
            for (int i = 0; i < 4; i++) {
                float4 t;
                t.x = to_tf32(pa[i].x); t.y = to_tf32(pa[i].y);
                t.z = to_tf32(pa[i].z); t.w = to_tf32(pa[i].w);
                *(float4*)(as + i * 4) = t;
                float4 u;
                u.x = to_tf32(pb[i].x); u.y = to_tf32(pb[i].y);
                u.z = to_tf32(pb[i].z); u.w = to_tf32(pb[i].w);
                *(float4*)(bs + i * 4) = u;
            }
            __syncthreads();
            buf ^= 1;
        }
    }

    // epilogue
    int row0 = by * 128 + wm;
    int col0 = bx * 128 + wn;
    #pragma unroll
    for (int mi = 0; mi < 4; mi++) {
        int r = row0 + mi * 16 + g;
        #pragma unroll
        for (int nj = 0; nj < 4; nj++) {
            int cc = col0 + nj * 8 + 2 * l;
            float v0 = acc[mi][nj][0], v1 = acc[mi][nj][1];
            float v2 = acc[mi][nj][2], v3 = acc[mi][nj][3];
            if (EPI == 2 || EPI == 3) {
                float b0 = bias[cc], b1 = bias[cc + 1];
                v0 += b0; v1 += b1; v2 += b0; v3 += b1;
            }
            if (EPI == 2) {
                v0 = gelu_exact(v0); v1 = gelu_exact(v1);
                v2 = gelu_exact(v2); v3 = gelu_exact(v3);
            }
            if (EPI == 1 || EPI == 3) {
                const float* r0p = res + (size_t)r * N + cc;
                const float* r1p = res + (size_t)(r + 8) * N + cc;
                v0 += r0p[0]; v1 += r0p[1];
                v2 += r1p[0]; v3 += r1p[1];
            }
            float2 lo = make_float2(v0, v1);
            float2 hi = make_float2(v2, v3);
            *(float2*)&C[(size_t)r * N + cc] = lo;
            *(float2*)&C[(size_t)(r + 8) * N + cc] = hi;
        }
    }
}

// ---------------- RoPE (in-place on q and k) ----------------
__global__ __launch_bounds__(256) void rope_kernel(float* __restrict__ q,
                                                   float* __restrict__ k) {
    int idx = blockIdx.x * blockDim.x + threadIdx.x;    // ROWS*NHEAD*32
    if (idx >= ROWS * NHEAD * 32) return;
    int pair = idx & 31;
    int h = (idx >> 5) & 15;
    int row = idx >> 9;
    int s = row & (SEQ - 1);
    float inv_freq = 1.0f / powf(10000.0f, (float)(2 * pair) * (1.0f / 64.0f));
    float f = (float)s * inv_freq;
    float cs = cosf(f), sn = sinf(f);
    size_t base = (size_t)row * D_MODEL + h * HEAD_DIM + 2 * pair;
    float q0 = q[base], q1 = q[base + 1];
    q[base]     = q0 * cs - q1 * sn;
    q[base + 1] = q1 * cs + q0 * sn;
    float k0 = k[base], k1 = k[base + 1];
    k[base]     = k0 * cs - k1 * sn;
    k[base + 1] = k1 * cs + k0 * sn;
}

// ---------------- Flash attention (fp32, non-causal) ----------------
__global__ __launch_bounds__(128, 1) void attn_kernel(const float* __restrict__ q,
                                                      const float* __restrict__ k,
                                                      const float* __restrict__ v,
                                                      float* __restrict__ out) {
    __shared__ float smem[8192];
    float* Ks = smem;              // [64][64]
    float* Vs = smem + 4096;       // [64][64]
    int t = threadIdx.x;
    int qtile = blockIdx.x;
    int bh = blockIdx.y;
    int b = bh >> 4, h = bh & 15;
    int hoff = h * HEAD_DIM;
    int qrow0 = b * SEQ + qtile * 128;

    float qreg[HEAD_DIM];
    {
        float* Qt = smem;          // [64][128]
        for (int i = t; i < 128 * 64; i += 128) {
            int r = i >> 6, d = i & 63;
            Qt[d * 128 + r] = q[(size_t)(qrow0 + r) * D_MODEL + hoff + d];
        }
        __syncthreads();
        #pragma unroll
        for (int d = 0; d < HEAD_DIM; d++) qreg[d] = Qt[d * 128 + t];
        __syncthreads();
    }

    float o[HEAD_DIM];
    #pragma unroll
    for (int d = 0; d < HEAD_DIM; d++) o[d] = 0.f;
    float m = -1e30f, l = 0.f;

    for (int kt = 0; kt < SEQ / 64; kt++) {
        for (int i = t; i < 64 * 64; i += 128) {
            int r = i >> 6, d = i & 63;
            size_t gg = (size_t)(b * SEQ + kt * 64 + r) * D_MODEL + hoff + d;
            Ks[i] = k[gg];
            Vs[i] = v[gg];
        }
        __syncthreads();
        #pragma unroll 4
        for (int j = 0; j < 64; j += 4) {
            const float* k0 = Ks + j * 64;
            const float* k1 = k0 + 64;
            const float* k2 = k0 + 128;
            const float* k3 = k0 + 192;
            float s0 = 0.f, s1 = 0.f, s2 = 0.f, s3 = 0.f;
            #pragma unroll
            for (int d = 0; d < HEAD_DIM; d++) {
                float qd = qreg[d];
                s0 += qd * k0[d];
                s1 += qd * k1[d];
                s2 += qd * k2[d];
                s3 += qd * k3[d];
            }
            s0 *= 0.125f; s1 *= 0.125f; s2 *= 0.125f; s3 *= 0.125f;
            float mn = fmaxf(fmaxf(s0, s1), fmaxf(s2, s3));
            if (mn > m) {
                float corr = expf(m - mn);
                l *= corr;
                #pragma unroll
                for (int d = 0; d < HEAD_DIM; d++) o[d] *= corr;
                m = mn;
            }
            float p0 = expf(s0 - m), p1 = expf(s1 - m);
            float p2 = expf(s2 - m), p3 = expf(s3 - m);
            l += p0 + p1 + p2 + p3;
            const float* v0 = Vs + j * 64;
            const float* v1 = v0 + 64;
            const float* v2 = v0 + 128;
            const float* v3 = v0 + 192;
            #pragma unroll
            for (int d = 0; d < HEAD_DIM; d++)
                o[d] += p0 * v0[d] + p1 * v1[d] + p2 * v2[d] + p3 * v3[d];
        }
        __syncthreads();
    }

    float inv_l = 1.0f / l;
    float* Ot = smem;
    #pragma unroll
    for (int d = 0; d < HEAD_DIM; d++) Ot[d * 128 + t] = o[d] * inv_l;
    __syncthreads();
    for (int i = t; i < 128 * 64; i += 128) {
        int r = i >> 6, d = i & 63;
        out[(size_t)(qrow0 + r) * D_MODEL + hoff + d] = Ot[d * 128 + r];
    }
}

// ---------------- launch ----------------
extern "C" void kernel_launch(void* const* d_in, const int* in_sizes, int n_in,
                              void* d_out, int out_size) {
    const float* inputs = (const float*)d_in[0];
    const float* ln1_g  = (const float*)d_in[1];
    const float* ln1_b  = (const float*)d_in[2];
    const float* Wq     = (const float*)d_in[3];
    const float* Wk     = (const float*)d_in[4];
    const float* Wv     = (const float*)d_in[5];
    const float* Wo     = (const float*)d_in[6];
    const float* ln2_g  = (const float*)d_in[7];
    const float* ln2_b  = (const float*)d_in[8];
    const float* Wfc2   = (const float*)d_in[9];
    const float* bfc2   = (const float*)d_in[10];
    const float* Wfc3   = (const float*)d_in[11];
    const float* bfc3   = (const float*)d_in[12];
    float* out = (float*)d_out;

    float *px, *pq, *pk, *pv, *patt, *pmlp, *pln2, *ph;
    cudaGetSymbolAddress((void**)&px,   g_x);
    cudaGetSymbolAddress((void**)&pq,   g_q);
    cudaGetSymbolAddress((void**)&pk,   g_k);
    cudaGetSymbolAddress((void**)&pv,   g_v);
    cudaGetSymbolAddress((void**)&patt, g_att);
    cudaGetSymbolAddress((void**)&pmlp, g_mlpin);
    cudaGetSymbolAddress((void**)&pln2, g_ln2);
    cudaGetSymbolAddress((void**)&ph,   g_h);

    cudaFuncSetAttribute(gemm_tf32<0>, cudaFuncAttributeMaxDynamicSharedMemorySize, GEMM_SMEM);
    cudaFuncSetAttribute(gemm_tf32<1>, cudaFuncAttributeMaxDynamicSharedMemorySize, GEMM_SMEM);
    cudaFuncSetAttribute(gemm_tf32<2>, cudaFuncAttributeMaxDynamicSharedMemorySize, GEMM_SMEM);
    cudaFuncSetAttribute(gemm_tf32<3>, cudaFuncAttributeMaxDynamicSharedMemorySize, GEMM_SMEM);

    // 1. x = LN1(inputs)
    ln_kernel<<<ROWS, 256>>>(inputs, ln1_g, ln1_b, px);

    // 2. q/k/v = x @ W{q,k,v}
    dim3 gqkv(D_MODEL / 128, ROWS / 128);
    gemm_tf32<0><<<gqkv, 256, GEMM_SMEM>>>(px, Wq, nullptr, nullptr, pq, ROWS, D_MODEL, D_MODEL);
    gemm_tf32<0><<<gqkv, 256, GEMM_SMEM>>>(px, Wk, nullptr, nullptr, pk, ROWS, D_MODEL, D_MODEL);
    gemm_tf32<0><<<gqkv, 256, GEMM_SMEM>>>(px, Wv, nullptr, nullptr, pv, ROWS, D_MODEL, D_MODEL);

    // 3. RoPE in-place on q,k
    int nrope = ROWS * NHEAD * 32;
    rope_kernel<<<(nrope + 255) / 256, 256>>>(pq, pk);

    // 4. attention
    attn_kernel<<<dim3(SEQ / 128, BATCH * NHEAD), 128>>>(pq, pk, pv, patt);

    // 5. mlp_in = attn @ Wo + inputs
    gemm_tf32<1><<<gqkv, 256, GEMM_SMEM>>>(patt, Wo, nullptr, inputs, pmlp, ROWS, D_MODEL, D_MODEL);

    // 6. ln2
    ln_kernel<<<ROWS, 256>>>(pmlp, ln2_g, ln2_b, pln2);

    // 7. h = gelu(ln2 @ Wfc2 + bfc2)
    gemm_tf32<2><<<dim3(MLP_DIM / 128, ROWS / 128), 256, GEMM_SMEM>>>(
        pln2, Wfc2, bfc2, nullptr, ph, ROWS, MLP_DIM, D_MODEL);

    // 8. out = h @ Wfc3 + bfc3 + mlp_in
    gemm_tf32<3><<<dim3(D_MODEL / 128, ROWS / 128), 256, GEMM_SMEM>>>(
        ph, Wfc3, bfc3, pmlp, out, ROWS, D_MODEL, MLP_DIM);
}

// round 6
// speedup vs baseline: 2.8662x; 2.6004x over previous
#include <cuda_runtime.h>
#include <cuda_bf16.h>
#include <math.h>
#include <stdint.h>

#define D_MODEL 1024
#define NHEAD 16
#define HEAD_DIM 64
#define MLP_DIM 4096
#define BATCH 2
#define SEQ 2048
#define ROWS (BATCH * SEQ)   // 4096

// ---------------- scratch buffers (device globals; no allocation) -------------
__device__ float g_x[ROWS * D_MODEL];      // ln1 output
__device__ float g_q[ROWS * D_MODEL];
__device__ float g_k[ROWS * D_MODEL];
__device__ float g_v[ROWS * D_MODEL];
__device__ float g_att[ROWS * D_MODEL];
__device__ float g_mlpin[ROWS * D_MODEL];
__device__ float g_ln2[ROWS * D_MODEL];
__device__ float g_h[ROWS * MLP_DIM];

// ---------------- LayerNorm ----------------
__global__ __launch_bounds__(256) void ln_kernel(const float* __restrict__ x,
                                                 const float* __restrict__ g,
                                                 const float* __restrict__ b,
                                                 float* __restrict__ out) {
    __shared__ float red[16];
    __shared__ float stats[2];
    int row = blockIdx.x;
    int tid = threadIdx.x;
    const float4* xr = (const float4*)(x + (size_t)row * D_MODEL);
    float4 v = xr[tid];
    float s  = v.x + v.y + v.z + v.w;
    float sq = v.x * v.x + v.y * v.y + v.z * v.z + v.w * v.w;
    #pragma unroll
    for (int o = 16; o > 0; o >>= 1) {
        s  += __shfl_xor_sync(0xffffffffu, s, o);
        sq += __shfl_xor_sync(0xffffffffu, sq, o);
    }
    int warp = tid >> 5, lane = tid & 31;
    if (lane == 0) { red[warp] = s; red[warp + 8] = sq; }
    __syncthreads();
    if (tid == 0) {
        float ts = 0.f, tq = 0.f;
        #pragma unroll
        for (int i = 0; i < 8; i++) { ts += red[i]; tq += red[i + 8]; }
        float mean = ts * (1.0f / D_MODEL);
        float var  = tq * (1.0f / D_MODEL) - mean * mean;
        stats[0] = mean;
        stats[1] = rsqrtf(var + 1e-5f);
    }
    __syncthreads();
    float mean = stats[0], inv = stats[1];
    const float4* gr = (const float4*)g;
    const float4* br = (const float4*)b;
    float4 gv = gr[tid], bv = br[tid];
    float4 ov;
    ov.x = (v.x - mean) * inv * gv.x + bv.x;
    ov.y = (v.y - mean) * inv * gv.y + bv.y;
    ov.z = (v.z - mean) * inv * gv.z + bv.z;
    ov.w = (v.w - mean) * inv * gv.w + bv.w;
    ((float4*)(out + (size_t)row * D_MODEL))[tid] = ov;
}

// ---------------- helpers ----------------
__device__ __forceinline__ float gelu_exact(float x) {
    return 0.5f * x * (1.0f + erff(x * 0.70710678118654752f));
}
__device__ __forceinline__ float to_tf32(float x) {
    uint32_t r;
    asm("cvt.rna.tf32.f32 %0, %1;" : "=r"(r) : "f"(x));
    return __uint_as_float(r);
}
__device__ __forceinline__ void mma_tf32(float* d, const uint32_t* a, const uint32_t* b) {
    asm volatile(
        "mma.sync.aligned.m16n8k8.row.col.f32.tf32.tf32.f32 "
        "{%0,%1,%2,%3}, {%4,%5,%6,%7}, {%8,%9}, {%0,%1,%2,%3};"
        : "+f"(d[0]), "+f"(d[1]), "+f"(d[2]), "+f"(d[3])
        : "r"(a[0]), "r"(a[1]), "r"(a[2]), "r"(a[3]), "r"(b[0]), "r"(b[1]));
}

// ---------------- tf32 tensor-core GEMM (generic) ----------------
// EPI: 0 = none, 1 = +res, 2 = +bias then gelu, 3 = +bias +res
#define ASTRIDE 36
#define BSTRIDE 136
#define ABUF (128 * ASTRIDE)
#define BBUF (32 * BSTRIDE)
#define GEMM_SMEM ((2 * ABUF + 2 * BBUF) * 4)

template <int EPI>
__global__ __launch_bounds__(256) void gemm_tf32(
    const float* __restrict__ A, const float* __restrict__ B,
    const float* __restrict__ bias, const float* __restrict__ res,
    float* __restrict__ C, int M, int N, int K)
{
    extern __shared__ float smem[];
    float* As = smem;
    float* Bs = smem + 2 * ABUF;

    int tid = threadIdx.x;
    int lane = tid & 31, wid = tid >> 5;
    int g = lane >> 2, l = lane & 3;
    int wm = (wid & 1) * 64;
    int wn = (wid >> 1) * 32;

    int bx = blockIdx.x, by = blockIdx.y;

    int ar = tid >> 1;
    int ac = (tid & 1) * 16;
    int br = tid >> 3;
    int bc = (tid & 7) * 16;

    const float* Ag = A + (size_t)(by * 128 + ar) * K + ac;
    const float* Bg = B + (size_t)br * N + bx * 128 + bc;

    float4 pa[4], pb[4];
    #pragma unroll
    for (int i = 0; i < 4; i++) {
        pa[i] = *(const float4*)(Ag + i * 4);
        pb[i] = *(const float4*)(Bg + i * 4);
    }

    float acc[4][4][4];
    #pragma unroll
    for (int mi = 0; mi < 4; mi++)
        #pragma unroll
        for (int nj = 0; nj < 4; nj++)
            #pragma unroll
            for (int r = 0; r < 4; r++) acc[mi][nj][r] = 0.f;

    int nIter = K / 32;
    int buf = 0;

    {
        float* as = As + ar * ASTRIDE + ac;
        float* bs = Bs + br * BSTRIDE + bc;
        #pragma unroll
        for (int i = 0; i < 4; i++) {
            float4 t;
            t.x = to_tf32(pa[i].x); t.y = to_tf32(pa[i].y);
            t.z = to_tf32(pa[i].z); t.w = to_tf32(pa[i].w);
            *(float4*)(as + i * 4) = t;
            float4 u;
            u.x = to_tf32(pb[i].x); u.y = to_tf32(pb[i].y);
            u.z = to_tf32(pb[i].z); u.w = to_tf32(pb[i].w);
            *(float4*)(bs + i * 4) = u;
        }
    }
    __syncthreads();

    for (int it = 0; it < nIter; it++) {
        if (it + 1 < nIter) {
            int k0 = (it + 1) * 32;
            #pragma unroll
            for (int i = 0; i < 4; i++) {
                pa[i] = *(const float4*)(Ag + k0 + i * 4);
                pb[i] = *(const float4*)(Bg + (size_t)k0 * N + i * 4);
            }
        }

        const float* ab = As + buf * ABUF;
        const float* bb = Bs + buf * BBUF;
        #pragma unroll
        for (int ks = 0; ks < 4; ks++) {
            int k8 = ks * 8;
            uint32_t af[4][4], bf[4][2];
            #pragma unroll
            for (int mi = 0; mi < 4; mi++) {
                const float* p = ab + (wm + mi * 16 + g) * ASTRIDE + k8 + l;
                af[mi][0] = __float_as_uint(p[0]);
                af[mi][1] = __float_as_uint(p[8 * ASTRIDE]);
                af[mi][2] = __float_as_uint(p[4]);
                af[mi][3] = __float_as_uint(p[8 * ASTRIDE + 4]);
            }
            #pragma unroll
            for (int nj = 0; nj < 4; nj++) {
                const float* p = bb + (k8 + l) * BSTRIDE + wn + nj * 8 + g;
                bf[nj][0] = __float_as_uint(p[0]);
                bf[nj][1] = __float_as_uint(p[4 * BSTRIDE]);
            }
            #pragma unroll
            for (int mi = 0; mi < 4; mi++)
                #pragma unroll
                for (int nj = 0; nj < 4; nj++)
                    mma_tf32(acc[mi][nj], af[mi], bf[nj]);
        }

        if (it + 1 < nIter) {
            float* as = As + (buf ^ 1) * ABUF + ar * ASTRIDE + ac;
            float* bs = Bs + (buf ^ 1) * BBUF + br * BSTRIDE + bc;
            #pragma unroll
            for (int i = 0; i < 4; i++) {
                float4 t;
                t.x = to_tf32(pa[i].x); t.y = to_tf32(pa[i].y);
                t.z = to_tf32(pa[i].z); t.w = to_tf32(pa[i].w);
                *(float4*)(as + i * 4) = t;
                float4 u;
                u.x = to_tf32(pb[i].x); u.y = to_tf32(pb[i].y);
                u.z = to_tf32(pb[i].z); u.w = to_tf32(pb[i].w);
                *(float4*)(bs + i * 4) = u;
            }
            __syncthreads();
            buf ^= 1;
        }
    }

    int row0 = by * 128 + wm;
    int col0 = bx * 128 + wn;
    #pragma unroll
    for (int mi = 0; mi < 4; mi++) {
        int r = row0 + mi * 16 + g;
        #pragma unroll
        for (int nj = 0; nj < 4; nj++) {
            int cc = col0 + nj * 8 + 2 * l;
            float v0 = acc[mi][nj][0], v1 = acc[mi][nj][1];
            float v2 = acc[mi][nj][2], v3 = acc[mi][nj][3];
            if (EPI == 2 || EPI == 3) {
                float b0 = bias[cc], b1 = bias[cc + 1];
                v0 += b0; v1 += b1; v2 += b0; v3 += b1;
            }
            if (EPI == 2) {
                v0 = gelu_exact(v0); v1 = gelu_exact(v1);
                v2 = gelu_exact(v2); v3 = gelu_exact(v3);
            }
            if (EPI == 1 || EPI == 3) {
                const float* r0p = res + (size_t)r * N + cc;
                const float* r1p = res + (size_t)(r + 8) * N + cc;
                v0 += r0p[0]; v1 += r0p[1];
                v2 += r1p[0]; v3 += r1p[1];
            }
            *(float2*)&C[(size_t)r * N + cc] = make_float2(v0, v1);
            *(float2*)&C[(size_t)(r + 8) * N + cc] = make_float2(v2, v3);
        }
    }
}

// ---------------- fused QKV GEMM with RoPE epilogue ----------------
// grid.x = 24: mat = bx>>3 (0=q,1=k,2=v), nx = bx&7.  K = N = 1024.
__global__ __launch_bounds__(256) void qkv_gemm(
    const float* __restrict__ A,
    const float* __restrict__ Wq, const float* __restrict__ Wk,
    const float* __restrict__ Wv,
    float* __restrict__ Oq, float* __restrict__ Ok, float* __restrict__ Ov)
{
    extern __shared__ float smem[];
    float* As = smem;
    float* Bs = smem + 2 * ABUF;

    const int N = D_MODEL, K = D_MODEL;
    int tid = threadIdx.x;
    int lane = tid & 31, wid = tid >> 5;
    int g = lane >> 2, l = lane & 3;
    int wm = (wid & 1) * 64;
    int wn = (wid >> 1) * 32;

    int mat = blockIdx.x >> 3;
    int nx  = blockIdx.x & 7;
    int by  = blockIdx.y;
    const float* B = (mat == 0) ? Wq : (mat == 1) ? Wk : Wv;
    float* C = (mat == 0) ? Oq : (mat == 1) ? Ok : Ov;

    int ar = tid >> 1;
    int ac = (tid & 1) * 16;
    int br = tid >> 3;
    int bc = (tid & 7) * 16;

    const float* Ag = A + (size_t)(by * 128 + ar) * K + ac;
    const float* Bg = B + (size_t)br * N + nx * 128 + bc;

    float4 pa[4], pb[4];
    #pragma unroll
    for (int i = 0; i < 4; i++) {
        pa[i] = *(const float4*)(Ag + i * 4);
        pb[i] = *(const float4*)(Bg + i * 4);
    }

    float acc[4][4][4];
    #pragma unroll
    for (int mi = 0; mi < 4; mi++)
        #pragma unroll
        for (int nj = 0; nj < 4; nj++)
            #pragma unroll
            for (int r = 0; r < 4; r++) acc[mi][nj][r] = 0.f;

    int nIter = K / 32;
    int buf = 0;

    {
        float* as = As + ar * ASTRIDE + ac;
        float* bs = Bs + br * BSTRIDE + bc;
        #pragma unroll
        for (int i = 0; i < 4; i++) {
            float4 t;
            t.x = to_tf32(pa[i].x); t.y = to_tf32(pa[i].y);
            t.z = to_tf32(pa[i].z); t.w = to_tf32(pa[i].w);
            *(float4*)(as + i * 4) = t;
            float4 u;
            u.x = to_tf32(pb[i].x); u.y = to_tf32(pb[i].y);
            u.z = to_tf32(pb[i].z); u.w = to_tf32(pb[i].w);
            *(float4*)(bs + i * 4) = u;
        }
    }
    __syncthreads();

    for (int it = 0; it < nIter; it++) {
        if (it + 1 < nIter) {
            int k0 = (it + 1) * 32;
            #pragma unroll
            for (int i = 0; i < 4; i++) {
                pa[i] = *(const float4*)(Ag + k0 + i * 4);
                pb[i] = *(const float4*)(Bg + (size_t)k0 * N + i * 4);
            }
        }
        const float* ab = As + buf * ABUF;
        const float* bb = Bs + buf * BBUF;
        #pragma unroll
        for (int ks = 0; ks < 4; ks++) {
            int k8 = ks * 8;
            uint32_t af[4][4], bf[4][2];
            #pragma unroll
            for (int mi = 0; mi < 4; mi++) {
                const float* p = ab + (wm + mi * 16 + g) * ASTRIDE + k8 + l;
                af[mi][0] = __float_as_uint(p[0]);
                af[mi][1] = __float_as_uint(p[8 * ASTRIDE]);
                af[mi][2] = __float_as_uint(p[4]);
                af[mi][3] = __float_as_uint(p[8 * ASTRIDE + 4]);
            }
            #pragma unroll
            for (int nj = 0; nj < 4; nj++) {
                const float* p = bb + (k8 + l) * BSTRIDE + wn + nj * 8 + g;
                bf[nj][0] = __float_as_uint(p[0]);
                bf[nj][1] = __float_as_uint(p[4 * BSTRIDE]);
            }
            #pragma unroll
            for (int mi = 0; mi < 4; mi++)
                #pragma unroll
                for (int nj = 0; nj < 4; nj++)
                    mma_tf32(acc[mi][nj], af[mi], bf[nj]);
        }
        if (it + 1 < nIter) {
            float* as = As + (buf ^ 1) * ABUF + ar * ASTRIDE + ac;
            float* bs = Bs + (buf ^ 1) * BBUF + br * BSTRIDE + bc;
            #pragma unroll
            for (int i = 0; i < 4; i++) {
                float4 t;
                t.x = to_tf32(pa[i].x); t.y = to_tf32(pa[i].y);
                t.z = to_tf32(pa[i].z); t.w = to_tf32(pa[i].w);
                *(float4*)(as + i * 4) = t;
                float4 u;
                u.x = to_tf32(pb[i].x); u.y = to_tf32(pb[i].y);
                u.z = to_tf32(pb[i].z); u.w = to_tf32(pb[i].w);
                *(float4*)(bs + i * 4) = u;
            }
            __syncthreads();
            buf ^= 1;
        }
    }

    int row0 = by * 128 + wm;
    int col0 = nx * 128 + wn;
    bool rope = (mat < 2);
    #pragma unroll
    for (int mi = 0; mi < 4; mi++) {
        int r = row0 + mi * 16 + g;
        int t0 = r & (SEQ - 1);
        #pragma unroll
        for (int nj = 0; nj < 4; nj++) {
            int cc = col0 + nj * 8 + 2 * l;
            float v0 = acc[mi][nj][0], v1 = acc[mi][nj][1];
            float v2 = acc[mi][nj][2], v3 = acc[mi][nj][3];
            if (rope) {
                int hd = cc & 63;
                int pi = hd >> 1;
                float invf = exp2f(-0.41524101186f * (float)pi);
                float a0 = (float)t0 * invf;
                float a1 = (float)(t0 + 8) * invf;
                float c0, s0, c1, s1;
                sincosf(a0, &s0, &c0);
                sincosf(a1, &s1, &c1);
                float n0 = v0 * c0 - v1 * s0;
                float n1 = v1 * c0 + v0 * s0;
                float n2 = v2 * c1 - v3 * s1;
                float n3 = v3 * c1 + v2 * s1;
                v0 = n0; v1 = n1; v2 = n2; v3 = n3;
            }
            *(float2*)&C[(size_t)r * D_MODEL + cc] = make_float2(v0, v1);
            *(float2*)&C[(size_t)(r + 8) * D_MODEL + cc] = make_float2(v2, v3);
        }
    }
}

// ---------------- MMA flash attention (tf32) ----------------
// block: 256 thr (8 warps), 128 q rows per block, warp = 16 rows; K-tile 64.
#define KSTR 68
#define ATT_SMEM ((64 * KSTR + 64 * KSTR + 128 * KSTR) * 4)   // Ks, Vs, Ps/Qs

__global__ __launch_bounds__(256) void attn_mma(const float* __restrict__ q,
                                                const float* __restrict__ k,
                                                const float* __restrict__ v,
                                                float* __restrict__ out) {
    extern __shared__ float sm[];
    float* Ks = sm;                    // [64][KSTR]
    float* Vs = sm + 64 * KSTR;        // [64][KSTR]
    float* Ps = sm + 128 * KSTR;       // [128][KSTR], also Q staging

    int tid = threadIdx.x;
    int lane = tid & 31, wid = tid >> 5;
    int g = lane >> 2, l = lane & 3;
    int wm = wid * 16;

    int qtile = blockIdx.x;
    int bh = blockIdx.y;
    int b = bh >> 4, h = bh & 15;
    int hoff = h * HEAD_DIM;
    int qrow0 = b * SEQ + qtile * 128;

    // stage Q (scaled, tf32) and preload A-frags into regs
    for (int i = tid; i < 128 * 16; i += 256) {
        int r = i >> 4, d4 = (i & 15) * 4;
        float4 qv = *(const float4*)(q + (size_t)(qrow0 + r) * D_MODEL + hoff + d4);
        float4 t;
        t.x = to_tf32(qv.x * 0.125f); t.y = to_tf32(qv.y * 0.125f);
        t.z = to_tf32(qv.z * 0.125f); t.w = to_tf32(qv.w * 0.125f);
        *(float4*)(Ps + r * KSTR + d4) = t;
    }
    __syncthreads();
    uint32_t qf[8][4];
    #pragma unroll
    for (int ks = 0; ks < 8; ks++) {
        const float* p = Ps + (wm + g) * KSTR + ks * 8 + l;
        qf[ks][0] = __float_as_uint(p[0]);
        qf[ks][1] = __float_as_uint(p[8 * KSTR]);
        qf[ks][2] = __float_as_uint(p[4]);
        qf[ks][3] = __float_as_uint(p[8 * KSTR + 4]);
    }

    float oa[8][4];
    #pragma unroll
    for (int nj = 0; nj < 8; nj++)
        #pragma unroll
        for (int r = 0; r < 4; r++) oa[nj][r] = 0.f;
    float m0 = -1e30f, m1 = -1e30f, ls0 = 0.f, ls1 = 0.f;

    for (int kt = 0; kt < SEQ / 64; kt++) {
        __syncthreads();   // previous tile's Vs/Ps fully consumed
        for (int i = tid; i < 64 * 16; i += 256) {
            int r = i >> 4, d4 = (i & 15) * 4;
            size_t gi = (size_t)(b * SEQ + kt * 64 + r) * D_MODEL + hoff + d4;
            float4 kv = *(const float4*)(k + gi);
            float4 tk;
            tk.x = to_tf32(kv.x); tk.y = to_tf32(kv.y);
            tk.z = to_tf32(kv.z); tk.w = to_tf32(kv.w);
            *(float4*)(Ks + r * KSTR + d4) = tk;
            float4 vv = *(const float4*)(v + gi);
            float4 tv;
            tv.x = to_tf32(vv.x); tv.y = to_tf32(vv.y);
            tv.z = to_tf32(vv.z); tv.w = to_tf32(vv.w);
            *(float4*)(Vs + r * KSTR + d4) = tv;
        }
        __syncthreads();

        // S = Q @ K^T   (m16 x n64 per warp)
        float sa[8][4];
        #pragma unroll
        for (int nj = 0; nj < 8; nj++)
            #pragma unroll
            for (int r = 0; r < 4; r++) sa[nj][r] = 0.f;
        #pragma unroll
        for (int ks = 0; ks < 8; ks++) {
            int k8 = ks * 8;
            #pragma unroll
            for (int nj = 0; nj < 8; nj++) {
                const float* p = Ks + (nj * 8 + g) * KSTR + k8 + l;
                uint32_t bf[2];
                bf[0] = __float_as_uint(p[0]);
                bf[1] = __float_as_uint(p[4]);
                mma_tf32(sa[nj], qf[ks], bf);
            }
        }

        // online softmax
        float mx0 = -1e30f, mx1 = -1e30f;
        #pragma unroll
        for (int nj = 0; nj < 8; nj++) {
            mx0 = fmaxf(mx0, fmaxf(sa[nj][0], sa[nj][1]));
            mx1 = fmaxf(mx1, fmaxf(sa[nj][2], sa[nj][3]));
        }
        mx0 = fmaxf(mx0, __shfl_xor_sync(0xffffffffu, mx0, 1));
        mx0 = fmaxf(mx0, __shfl_xor_sync(0xffffffffu, mx0, 2));
        mx1 = fmaxf(mx1, __shfl_xor_sync(0xffffffffu, mx1, 1));
        mx1 = fmaxf(mx1, __shfl_xor_sync(0xffffffffu, mx1, 2));
        float nm0 = fmaxf(m0, mx0), nm1 = fmaxf(m1, mx1);
        float sc0 = __expf(m0 - nm0), sc1 = __expf(m1 - nm1);
        m0 = nm0; m1 = nm1;
        ls0 *= sc0; ls1 *= sc1;
        #pragma unroll
        for (int nj = 0; nj < 8; nj++) {
            oa[nj][0] *= sc0; oa[nj][1] *= sc0;
            oa[nj][2] *= sc1; oa[nj][3] *= sc1;
        }

        // P = exp(S - m) -> smem (per-warp private rows)
        float* pw0 = Ps + (wm + g) * KSTR + 2 * l;
        float* pw1 = Ps + (wm + g + 8) * KSTR + 2 * l;
        #pragma unroll
        for (int nj = 0; nj < 8; nj++) {
            float p0 = __expf(sa[nj][0] - m0);
            float p1 = __expf(sa[nj][1] - m0);
            float p2 = __expf(sa[nj][2] - m1);
            float p3 = __expf(sa[nj][3] - m1);
            ls0 += p0 + p1;
            ls1 += p2 + p3;
            *(float2*)(pw0 + nj * 8) = make_float2(to_tf32(p0), to_tf32(p1));
            *(float2*)(pw1 + nj * 8) = make_float2(to_tf32(p2), to_tf32(p3));
        }
        __syncwarp();

        // O += P @ V
        #pragma unroll
        for (int ks = 0; ks < 8; ks++) {
            int k8 = ks * 8;
            uint32_t pf[4];
            const float* pp = Ps + (wm + g) * KSTR + k8 + l;
            pf[0] = __float_as_uint(pp[0]);
            pf[1] = __float_as_uint(pp[8 * KSTR]);
            pf[2] = __float_as_uint(pp[4]);
            pf[3] = __float_as_uint(pp[8 * KSTR + 4]);
            #pragma unroll
            for (int nj = 0; nj < 8; nj++) {
                const float* vp = Vs + (k8 + l) * KSTR + nj * 8 + g;
                uint32_t vf[2];
                vf[0] = __float_as_uint(vp[0]);
                vf[1] = __float_as_uint(vp[4 * KSTR]);
                mma_tf32(oa[nj], pf, vf);
            }
        }
    }

    ls0 += __shfl_xor_sync(0xffffffffu, ls0, 1);
    ls0 += __shfl_xor_sync(0xffffffffu, ls0, 2);
    ls1 += __shfl_xor_sync(0xffffffffu, ls1, 1);
    ls1 += __shfl_xor_sync(0xffffffffu, ls1, 2);
    float inv0 = 1.0f / ls0, inv1 = 1.0f / ls1;

    int r0 = qrow0 + wm + g;
    #pragma unroll
    for (int nj = 0; nj < 8; nj++) {
        int cc = hoff + nj * 8 + 2 * l;
        *(float2*)&out[(size_t)r0 * D_MODEL + cc] =
            make_float2(oa[nj][0] * inv0, oa[nj][1] * inv0);
        *(float2*)&out[(size_t)(r0 + 8) * D_MODEL + cc] =
            make_float2(oa[nj][2] * inv1, oa[nj][3] * inv1);
    }
}

// ---------------- launch ----------------
extern "C" void kernel_launch(void* const* d_in, const int* in_sizes, int n_in,
                              void* d_out, int out_size) {
    const float* inputs = (const float*)d_in[0];
    const float* ln1_g  = (const float*)d_in[1];
    const float* ln1_b  = (const float*)d_in[2];
    const float* Wq     = (const float*)d_in[3];
    const float* Wk     = (const float*)d_in[4];
    const float* Wv     = (const float*)d_in[5];
    const float* Wo     = (const float*)d_in[6];
    const float* ln2_g  = (const float*)d_in[7];
    const float* ln2_b  = (const float*)d_in[8];
    const float* Wfc2   = (const float*)d_in[9];
    const float* bfc2   = (const float*)d_in[10];
    const float* Wfc3   = (const float*)d_in[11];
    const float* bfc3   = (const float*)d_in[12];
    float* out = (float*)d_out;

    float *px, *pq, *pk, *pv, *patt, *pmlp, *pln2, *ph;
    cudaGetSymbolAddress((void**)&px,   g_x);
    cudaGetSymbolAddress((void**)&pq,   g_q);
    cudaGetSymbolAddress((void**)&pk,   g_k);
    cudaGetSymbolAddress((void**)&pv,   g_v);
    cudaGetSymbolAddress((void**)&patt, g_att);
    cudaGetSymbolAddress((void**)&pmlp, g_mlpin);
    cudaGetSymbolAddress((void**)&pln2, g_ln2);
    cudaGetSymbolAddress((void**)&ph,   g_h);

    cudaFuncSetAttribute(gemm_tf32<1>, cudaFuncAttributeMaxDynamicSharedMemorySize, GEMM_SMEM);
    cudaFuncSetAttribute(gemm_tf32<2>, cudaFuncAttributeMaxDynamicSharedMemorySize, GEMM_SMEM);
    cudaFuncSetAttribute(gemm_tf32<3>, cudaFuncAttributeMaxDynamicSharedMemorySize, GEMM_SMEM);
    cudaFuncSetAttribute(qkv_gemm,     cudaFuncAttributeMaxDynamicSharedMemorySize, GEMM_SMEM);
    cudaFuncSetAttribute(attn_mma,     cudaFuncAttributeMaxDynamicSharedMemorySize, ATT_SMEM);

    // 1. x = LN1(inputs)
    ln_kernel<<<ROWS, 256>>>(inputs, ln1_g, ln1_b, px);

    // 2+3. fused QKV GEMM with RoPE epilogue
    qkv_gemm<<<dim3(24, ROWS / 128), 256, GEMM_SMEM>>>(px, Wq, Wk, Wv, pq, pk, pv);

    // 4. attention (tensor-core flash)
    attn_mma<<<dim3(SEQ / 128, BATCH * NHEAD), 256, ATT_SMEM>>>(pq, pk, pv, patt);

    // 5. mlp_in = attn @ Wo + inputs
    dim3 gqkv(D_MODEL / 128, ROWS / 128);
    gemm_tf32<1><<<gqkv, 256, GEMM_SMEM>>>(patt, Wo, nullptr, inputs, pmlp, ROWS, D_MODEL, D_MODEL);

    // 6. ln2
    ln_kernel<<<ROWS, 256>>>(pmlp, ln2_g, ln2_b, pln2);

    // 7. h = gelu(ln2 @ Wfc2 + bfc2)
    gemm_tf32<2><<<dim3(MLP_DIM / 128, ROWS / 128), 256, GEMM_SMEM>>>(
        pln2, Wfc2, bfc2, nullptr, ph, ROWS, MLP_DIM, D_MODEL);

    // 8. out = h @ Wfc3 + bfc3 + mlp_in
    gemm_tf32<3><<<dim3(D_MODEL / 128, ROWS / 128), 256, GEMM_SMEM>>>(
        ph, Wfc3, bfc3, pmlp, out, ROWS, D_MODEL, MLP_DIM);
}